// round 15
// baseline (speedup 1.0000x reference)
#include <cuda_runtime.h>
#include <cuda_bf16.h>
#include <math.h>
#include <stdint.h>

#define B_   16
#define C_   256
#define N_   4096
#define NH_  4
#define HD_  64
#define G_   32
#define K3   768   // 3*C
#define NSPLIT 8

// ------------------------- scratch (device globals; no allocation) ---------
__device__ float g_mean[B_ * G_];
__device__ float g_rstd[B_ * G_];
__device__ __nv_bfloat16 g_ht[(size_t)B_ * N_ * C_];   // GN out, [b][n][c] bf16
__device__ __nv_bfloat16 g_at[(size_t)B_ * N_ * C_];   // attn out, [b][n][c] bf16
__device__ __nv_bfloat16 g_qkvh[(size_t)B_ * K3 * N_]; // qkv, [b][768][n] bf16
__device__ float2 g_qpart[B_ * C_ * 64];               // per-(row, chunk) partial {max, sumexp}
__device__ float2 g_qstat[B_ * C_];                    // per-(b,c) q row: {max, 1/sumexp}
__device__ float g_ctxp[(size_t)NSPLIT * B_ * NH_ * HD_ * HD_];
__device__ __nv_bfloat16 g_ctxT[B_ * NH_ * HD_ * HD_]; // reduced ctx^T, [b][h][e][d] bf16
__device__ int g_ctr[B_ * NH_];                        // split-K completion counters (zero-init)
__device__ __nv_bfloat16 g_wqkv[K3 * C_];
__device__ __nv_bfloat16 g_wout[C_ * C_];

// ------------------------- helpers -----------------------------------------
__device__ __forceinline__ uint32_t smem_u32(const void* p) {
    uint32_t a;
    asm("{ .reg .u64 t; cvta.to.shared.u64 t, %1; cvt.u32.u64 %0, t; }" : "=r"(a) : "l"(p));
    return a;
}

#define LDSM_X4(r, addr) \
    asm volatile("ldmatrix.sync.aligned.m8n8.x4.shared.b16 {%0,%1,%2,%3}, [%4];" \
        : "=r"((r)[0]), "=r"((r)[1]), "=r"((r)[2]), "=r"((r)[3]) : "r"(addr))

__device__ __forceinline__ void mma16816(float* c, const uint32_t* a,
                                         uint32_t b0, uint32_t b1) {
    asm volatile(
        "mma.sync.aligned.m16n8k16.row.col.f32.bf16.bf16.f32 "
        "{%0,%1,%2,%3}, {%4,%5,%6,%7}, {%8,%9}, {%0,%1,%2,%3};"
        : "+f"(c[0]), "+f"(c[1]), "+f"(c[2]), "+f"(c[3])
        : "r"(a[0]), "r"(a[1]), "r"(a[2]), "r"(a[3]), "r"(b0), "r"(b1));
}

__device__ __forceinline__ float warpReduceSum(float v) {
    #pragma unroll
    for (int o = 16; o > 0; o >>= 1) v += __shfl_xor_sync(0xffffffffu, v, o);
    return v;
}
__device__ __forceinline__ float warpReduceMax(float v) {
    #pragma unroll
    for (int o = 16; o > 0; o >>= 1) v = fmaxf(v, __shfl_xor_sync(0xffffffffu, v, o));
    return v;
}

// ------------------------- 1. merged: GroupNorm stats + weight convert -----
__global__ void pre_kernel(const float* __restrict__ x,
                           const float* __restrict__ qkv_w,
                           const float* __restrict__ out_w) {
    if (blockIdx.x >= 512) {
        int i = (blockIdx.x - 512) * 256 + threadIdx.x;
        if (i < K3 * C_) g_wqkv[i] = __float2bfloat16(qkv_w[i]);
        else             g_wout[i - K3 * C_] = __float2bfloat16(out_w[i - K3 * C_]);
        return;
    }
    int bg = blockIdx.x;
    const float4* p = reinterpret_cast<const float4*>(x) + (size_t)bg * 8192;
    float s = 0.f, ss = 0.f;
    for (int i = threadIdx.x; i < 8192; i += 256) {
        float4 v = p[i];
        s  += v.x + v.y + v.z + v.w;
        ss += v.x * v.x + v.y * v.y + v.z * v.z + v.w * v.w;
    }
    __shared__ float sm1[8], sm2[8];
    s  = warpReduceSum(s);
    ss = warpReduceSum(ss);
    int w = threadIdx.x >> 5, l = threadIdx.x & 31;
    if (l == 0) { sm1[w] = s; sm2[w] = ss; }
    __syncthreads();
    if (threadIdx.x == 0) {
        float S = 0.f, SS = 0.f;
        #pragma unroll
        for (int i = 0; i < 8; i++) { S += sm1[i]; SS += sm2[i]; }
        float m   = S * (1.f / 32768.f);
        float var = SS * (1.f / 32768.f) - m * m;
        g_mean[bg] = m;
        g_rstd[bg] = rsqrtf(var + 1e-5f);
    }
}

// ------------------------- 2. GroupNorm apply + transpose to bf16 ----------
__global__ void gn_apply_t_kernel(const float* __restrict__ x,
                                  const float* __restrict__ gw,
                                  const float* __restrict__ gb) {
    __shared__ float s[64][65];
    int b = blockIdx.z, c0 = blockIdx.y * 64, n0 = blockIdx.x * 64;
    int tid = threadIdx.x;
    #pragma unroll
    for (int i = 0; i < 4; i++) {
        int idx = i * 256 + tid;
        int c = idx >> 4, nq = idx & 15;
        int cc = c0 + c;
        int bg = b * G_ + (cc >> 3);
        float sc = gw[cc] * g_rstd[bg];
        float sh = gb[cc] - g_mean[bg] * sc;
        float4 v = *reinterpret_cast<const float4*>(&x[((size_t)b * C_ + cc) * N_ + n0 + nq * 4]);
        s[c][nq * 4 + 0] = v.x * sc + sh;
        s[c][nq * 4 + 1] = v.y * sc + sh;
        s[c][nq * 4 + 2] = v.z * sc + sh;
        s[c][nq * 4 + 3] = v.w * sc + sh;
    }
    __syncthreads();
    #pragma unroll
    for (int i = 0; i < 2; i++) {
        int idx = i * 256 + tid;
        int n = idx >> 3, cq = idx & 7;
        __nv_bfloat16 tmp[8];
        #pragma unroll
        for (int j = 0; j < 8; j++) tmp[j] = __float2bfloat16(s[cq * 8 + j][n]);
        *reinterpret_cast<uint4*>(&g_ht[((size_t)b * N_ + n0 + n) * C_ + c0 + cq * 8]) =
            *reinterpret_cast<uint4*>(tmp);
    }
}

// ------------------------- 3. HMMA bf16 GEMM + fused q-stat partials -------
#define GEMM_SMEM_BYTES 65536

__global__ __launch_bounds__(128) void hmma_gemm_kernel(
    const float* __restrict__ bias, float* __restrict__ Cout_ext,
    const float* __restrict__ Resid, int Mtotal, int which)
{
    extern __shared__ char smem[];
    const __nv_bfloat16* W    = which ? g_wout : g_wqkv;
    const __nv_bfloat16* Bact = which ? g_at   : g_ht;

    int b = blockIdx.z;
    int m0 = blockIdx.y * 128, n0 = blockIdx.x * 128;
    int tid = threadIdx.x, lane = tid & 31, wid = tid >> 5;
    int wm = (wid >> 1) * 64, wn = (wid & 1) * 64;

    const __nv_bfloat16* Asrc = W + (size_t)m0 * C_;
    const __nv_bfloat16* Bsrc = Bact + ((size_t)b * N_ + n0) * C_;
    uint32_t sbase = smem_u32(smem);

    auto issue = [&](int buf, int k0) {
        uint32_t abase = sbase + buf * 32768;
        uint32_t bbase = abase + 16384;
        #pragma unroll
        for (int i = 0; i < 8; i++) {
            int j = i * 128 + tid;
            int r = j >> 3, q = j & 7;
            uint32_t sw = (uint32_t)((q * 16) ^ ((r & 7) * 16));
            const void* sa = Asrc + (size_t)r * C_ + k0 + q * 8;
            const void* sb = Bsrc + (size_t)r * C_ + k0 + q * 8;
            asm volatile("cp.async.cg.shared.global [%0], [%1], 16;" :: "r"(abase + r * 128 + sw), "l"(sa));
            asm volatile("cp.async.cg.shared.global [%0], [%1], 16;" :: "r"(bbase + r * 128 + sw), "l"(sb));
        }
        asm volatile("cp.async.commit_group;" ::: "memory");
    };

    float acc[4][8][4];
    #pragma unroll
    for (int i = 0; i < 4; i++)
        #pragma unroll
        for (int j = 0; j < 8; j++)
            #pragma unroll
            for (int k = 0; k < 4; k++) acc[i][j][k] = 0.f;

    issue(0, 0);

    #pragma unroll
    for (int kt = 0; kt < 4; kt++) {
        if (kt < 3) {
            issue((kt + 1) & 1, (kt + 1) * 64);
            asm volatile("cp.async.wait_group 1;" ::: "memory");
        } else {
            asm volatile("cp.async.wait_group 0;" ::: "memory");
        }
        __syncthreads();
        uint32_t abase = sbase + (kt & 1) * 32768;
        uint32_t bbase = abase + 16384;
        #pragma unroll
        for (int s = 0; s < 4; s++) {
            uint32_t a[4][4], bg[4][4];
            #pragma unroll
            for (int mt = 0; mt < 4; mt++) {
                int row = wm + mt * 16 + (lane & 15);
                uint32_t col = (uint32_t)(s * 32 + (lane >> 4) * 16);
                LDSM_X4(a[mt], abase + row * 128 + (col ^ ((row & 7) * 16)));
            }
            #pragma unroll
            for (int nt2 = 0; nt2 < 4; nt2++) {
                int row = wn + nt2 * 16 + (lane & 7) + ((lane >> 4) & 1) * 8;
                uint32_t col = (uint32_t)(s * 32 + ((lane >> 3) & 1) * 16);
                LDSM_X4(bg[nt2], bbase + row * 128 + (col ^ ((row & 7) * 16)));
            }
            #pragma unroll
            for (int mt = 0; mt < 4; mt++)
                #pragma unroll
                for (int nt = 0; nt < 8; nt++)
                    mma16816(acc[mt][nt], a[mt],
                             bg[nt >> 1][(nt & 1) * 2], bg[nt >> 1][(nt & 1) * 2 + 1]);
        }
        __syncthreads();
    }

    size_t cb = (size_t)b * Mtotal * N_;
    int g = lane >> 2, tq = (lane & 3) * 2;
    #pragma unroll
    for (int mt = 0; mt < 4; mt++) {
        int rbase = m0 + wm + mt * 16 + g;
        float bv0 = bias[rbase], bv1 = bias[rbase + 8];
        #pragma unroll
        for (int nt = 0; nt < 8; nt++) {
            int cl = n0 + wn + nt * 8 + tq;
            size_t o0 = cb + (size_t)rbase * N_ + cl;
            size_t o1 = o0 + (size_t)8 * N_;
            if (which == 0) {
                *reinterpret_cast<__nv_bfloat162*>(&g_qkvh[o0]) =
                    __floats2bfloat162_rn(acc[mt][nt][0] + bv0, acc[mt][nt][1] + bv0);
                *reinterpret_cast<__nv_bfloat162*>(&g_qkvh[o1]) =
                    __floats2bfloat162_rn(acc[mt][nt][2] + bv1, acc[mt][nt][3] + bv1);
            } else {
                float2 r0 = *reinterpret_cast<const float2*>(&Resid[o0]);
                float2 r1 = *reinterpret_cast<const float2*>(&Resid[o1]);
                float2 v0 = make_float2(acc[mt][nt][0] + bv0 + r0.x, acc[mt][nt][1] + bv0 + r0.y);
                float2 v1 = make_float2(acc[mt][nt][2] + bv1 + r1.x, acc[mt][nt][3] + bv1 + r1.y);
                *reinterpret_cast<float2*>(&Cout_ext[o0]) = v0;
                *reinterpret_cast<float2*>(&Cout_ext[o1]) = v1;
            }
        }
        // fused partial q-softmax stats for q rows (m < 256)
        if (which == 0 && m0 < 256) {
            float m0f = -1e30f, m1f = -1e30f;
            #pragma unroll
            for (int nt = 0; nt < 8; nt++) {
                m0f = fmaxf(m0f, fmaxf(acc[mt][nt][0], acc[mt][nt][1]));
                m1f = fmaxf(m1f, fmaxf(acc[mt][nt][2], acc[mt][nt][3]));
            }
            m0f += bv0; m1f += bv1;
            float s0 = 0.f, s1 = 0.f;
            #pragma unroll
            for (int nt = 0; nt < 8; nt++) {
                s0 += __expf(acc[mt][nt][0] + bv0 - m0f) + __expf(acc[mt][nt][1] + bv0 - m0f);
                s1 += __expf(acc[mt][nt][2] + bv1 - m1f) + __expf(acc[mt][nt][3] + bv1 - m1f);
            }
            #pragma unroll
            for (int off = 1; off < 4; off <<= 1) {
                float mo0 = __shfl_xor_sync(0xffffffffu, m0f, off);
                float so0 = __shfl_xor_sync(0xffffffffu, s0, off);
                float nm0 = fmaxf(m0f, mo0);
                s0 = s0 * __expf(m0f - nm0) + so0 * __expf(mo0 - nm0);
                m0f = nm0;
                float mo1 = __shfl_xor_sync(0xffffffffu, m1f, off);
                float so1 = __shfl_xor_sync(0xffffffffu, s1, off);
                float nm1 = fmaxf(m1f, mo1);
                s1 = s1 * __expf(m1f - nm1) + so1 * __expf(mo1 - nm1);
                m1f = nm1;
            }
            if ((lane & 3) == 0) {
                int chunk = (n0 >> 7) * 2 + (wn >> 6);
                g_qpart[(b * 256 + rbase) * 64 + chunk]     = make_float2(m0f, s0);
                g_qpart[(b * 256 + rbase + 8) * 64 + chunk] = make_float2(m1f, s1);
            }
        }
    }
}

// ------------------------- 4. context + inline reduce + qstat2 (merged) ----
// blocks [0,512): context split-K HMMA; last split per (b,h) reduces -> g_ctxT
// blocks [512,1536): qstat2, 4 rows per block (4 warps)
__global__ __launch_bounds__(128) void context_hmma_kernel() {
    __shared__ char smem[32768];
    int bid = blockIdx.x;
    int tid = threadIdx.x, lane = tid & 31, wid = tid >> 5;

    if (bid >= 512) {
        // ---- qstat2: reduce 64 partials per row ----
        int row = (bid - 512) * 4 + wid;
        float2 a = g_qpart[row * 64 + lane];
        float2 c = g_qpart[row * 64 + 32 + lane];
        float m = fmaxf(a.x, c.x);
        float s = a.y * __expf(a.x - m) + c.y * __expf(c.x - m);
        #pragma unroll
        for (int off = 16; off > 0; off >>= 1) {
            float mo = __shfl_xor_sync(0xffffffffu, m, off);
            float so = __shfl_xor_sync(0xffffffffu, s, off);
            float nm = fmaxf(m, mo);
            s = s * __expf(m - nm) + so * __expf(mo - nm);
            m = nm;
        }
        if (lane == 0) g_qstat[row] = make_float2(m, 1.f / s);
        return;
    }

    int ns = bid & 7, h = (bid >> 3) & 3, b = bid >> 5;
    const __nv_bfloat16* Kp = g_qkvh + ((size_t)b * K3 + 256 + h * 64) * N_;
    const __nv_bfloat16* Vp = g_qkvh + ((size_t)b * K3 + 512 + h * 64) * N_;
    uint32_t sbase = smem_u32(smem);
    int n0 = ns * (N_ / NSPLIT);

    auto issue = [&](int buf, int k0) {
        uint32_t kb = sbase + buf * 16384;
        uint32_t vb = kb + 8192;
        #pragma unroll
        for (int i = 0; i < 4; i++) {
            int j = i * 128 + tid;
            int r = j >> 3, q = j & 7;
            uint32_t sw = (uint32_t)((q * 16) ^ ((r & 7) * 16));
            const void* sk = Kp + (size_t)r * N_ + k0 + q * 8;
            const void* sv = Vp + (size_t)r * N_ + k0 + q * 8;
            asm volatile("cp.async.cg.shared.global [%0], [%1], 16;" :: "r"(kb + r * 128 + sw), "l"(sk));
            asm volatile("cp.async.cg.shared.global [%0], [%1], 16;" :: "r"(vb + r * 128 + sw), "l"(sv));
        }
        asm volatile("cp.async.commit_group;" ::: "memory");
    };

    auto ktile_softmax = [&](uint32_t kb) {
        int colq = tid >> 1, half = tid & 1;
        __nv_bfloat16* ks = reinterpret_cast<__nv_bfloat16*>(smem) + (kb - sbase) / 2;
        float v[32];
        float mx = -1e30f;
        #pragma unroll
        for (int j = 0; j < 32; j++) {
            int d = half * 32 + j;
            uint32_t off = (uint32_t)(d * 128 + ((colq * 2) ^ ((d & 7) * 16)));
            v[j] = __bfloat162float(ks[off / 2]);
            mx = fmaxf(mx, v[j]);
        }
        mx = fmaxf(mx, __shfl_xor_sync(0xffffffffu, mx, 1));
        float s = 0.f;
        #pragma unroll
        for (int j = 0; j < 32; j++) { v[j] = __expf(v[j] - mx); s += v[j]; }
        s += __shfl_xor_sync(0xffffffffu, s, 1);
        float inv = 1.f / s;
        #pragma unroll
        for (int j = 0; j < 32; j++) {
            int d = half * 32 + j;
            uint32_t off = (uint32_t)(d * 128 + ((colq * 2) ^ ((d & 7) * 16)));
            ks[off / 2] = __float2bfloat16(v[j] * inv);
        }
    };

    float acc[8][4];
    #pragma unroll
    for (int i = 0; i < 8; i++)
        #pragma unroll
        for (int j = 0; j < 4; j++) acc[i][j] = 0.f;

    issue(0, n0);
    #pragma unroll
    for (int kt = 0; kt < 8; kt++) {
        if (kt < 7) {
            issue((kt + 1) & 1, n0 + (kt + 1) * 64);
            asm volatile("cp.async.wait_group 1;" ::: "memory");
        } else {
            asm volatile("cp.async.wait_group 0;" ::: "memory");
        }
        __syncthreads();
        uint32_t kb = sbase + (kt & 1) * 16384;
        uint32_t vb = kb + 8192;
        ktile_softmax(kb);
        __syncthreads();
        #pragma unroll
        for (int s = 0; s < 4; s++) {
            uint32_t a[4], bg[4][4];
            int row = wid * 16 + (lane & 15);
            uint32_t col = (uint32_t)(s * 32 + (lane >> 4) * 16);
            LDSM_X4(a, kb + row * 128 + (col ^ ((row & 7) * 16)));
            #pragma unroll
            for (int nt2 = 0; nt2 < 4; nt2++) {
                int rw = nt2 * 16 + (lane & 7) + ((lane >> 4) & 1) * 8;
                uint32_t cl = (uint32_t)(s * 32 + ((lane >> 3) & 1) * 16);
                LDSM_X4(bg[nt2], vb + rw * 128 + (cl ^ ((rw & 7) * 16)));
            }
            #pragma unroll
            for (int nt = 0; nt < 8; nt++)
                mma16816(acc[nt], a, bg[nt >> 1][(nt & 1) * 2], bg[nt >> 1][(nt & 1) * 2 + 1]);
        }
        __syncthreads();
    }
    int bh = b * NH_ + h;
    float* cp = g_ctxp + (((size_t)ns * B_ * NH_) + bh) * (HD_ * HD_);
    int g = lane >> 2, tq = (lane & 3) * 2;
    int row = wid * 16 + g;
    #pragma unroll
    for (int nt = 0; nt < 8; nt++) {
        int col = nt * 8 + tq;
        cp[row * 64 + col]           = acc[nt][0];
        cp[row * 64 + col + 1]       = acc[nt][1];
        cp[(row + 8) * 64 + col]     = acc[nt][2];
        cp[(row + 8) * 64 + col + 1] = acc[nt][3];
    }

    // last-arriving split reduces all partials for this (b,h) -> g_ctxT [e][d]
    __threadfence();
    __shared__ int s_last;
    __syncthreads();
    if (tid == 0) {
        int old = atomicAdd(&g_ctr[bh], 1);
        s_last = (old == NSPLIT - 1) ? 1 : 0;
    }
    __syncthreads();
    if (s_last) {
        __threadfence();   // acquire: make other splits' writes visible
        int base = bh * (HD_ * HD_);
        for (int i = tid; i < HD_ * HD_; i += 128) {
            int e = i >> 6, d = i & 63;
            float s = 0.f;
            #pragma unroll
            for (int sp = 0; sp < NSPLIT; sp++)
                s += g_ctxp[(size_t)sp * B_ * NH_ * HD_ * HD_ + base + d * 64 + e];
            g_ctxT[base + i] = __float2bfloat16(s);
        }
        if (tid == 0) g_ctr[bh] = 0;   // reset for next graph replay
    }
}

// ------------------------- 5. fused softmax(q)+transpose + ctx GEMM --------
__global__ __launch_bounds__(128) void apply_ctx_fused_kernel() {
    __shared__ float s[64][65];
    __shared__ float2 st[64];
    __shared__ char asmem[16384];
    __shared__ char bsmem[8192];
    int b = blockIdx.z, h = blockIdx.y, n0 = blockIdx.x * 128;
    int tid = threadIdx.x, lane = tid & 31, wid = tid >> 5;
    uint32_t abase = smem_u32(asmem), bbase = smem_u32(bsmem);

    const __nv_bfloat16* Qp = g_qkvh + ((size_t)b * K3 + h * 64) * N_;
    const __nv_bfloat16* Bp = g_ctxT + (b * NH_ + h) * (HD_ * HD_);

    #pragma unroll
    for (int i = 0; i < 4; i++) {
        int j = i * 128 + tid;
        int r = j >> 3, q = j & 7;
        uint32_t sw = (uint32_t)((q * 16) ^ ((r & 7) * 16));
        const void* sb = Bp + (size_t)r * HD_ + q * 8;
        asm volatile("cp.async.cg.shared.global [%0], [%1], 16;" :: "r"(bbase + r * 128 + sw), "l"(sb));
    }
    asm volatile("cp.async.commit_group;" ::: "memory");

    if (tid < 64) st[tid] = g_qstat[b * 256 + h * 64 + tid];

    #pragma unroll
    for (int half = 0; half < 2; half++) {
        int nh = n0 + half * 64;
        __syncthreads();
        #pragma unroll
        for (int i = 0; i < 4; i++) {
            int j = i * 128 + tid;
            int r = j >> 3, q8 = j & 7;
            uint4 u = *reinterpret_cast<const uint4*>(&Qp[(size_t)r * N_ + nh + q8 * 8]);
            const __nv_bfloat162* hh = reinterpret_cast<const __nv_bfloat162*>(&u);
            float2 ms = st[r];
            #pragma unroll
            for (int k = 0; k < 4; k++) {
                float2 f = __bfloat1622float2(hh[k]);
                s[r][q8 * 8 + 2 * k]     = __expf(f.x - ms.x) * ms.y;
                s[r][q8 * 8 + 2 * k + 1] = __expf(f.y - ms.x) * ms.y;
            }
        }
        __syncthreads();
        #pragma unroll
        for (int i = 0; i < 4; i++) {
            int j = i * 128 + tid;
            int n = j >> 3, cq = j & 7;
            __nv_bfloat16 tmp[8];
            #pragma unroll
            for (int k = 0; k < 8; k++) tmp[k] = __float2bfloat16(s[cq * 8 + k][n]);
            int row = half * 64 + n;
            uint32_t sw = (uint32_t)((cq * 16) ^ ((row & 7) * 16));
            *reinterpret_cast<uint4*>(asmem + row * 128 + sw) = *reinterpret_cast<uint4*>(tmp);
        }
    }
    asm volatile("cp.async.wait_group 0;" ::: "memory");
    __syncthreads();

    float acc[2][8][4];
    #pragma unroll
    for (int i = 0; i < 2; i++)
        #pragma unroll
        for (int j = 0; j < 8; j++)
            #pragma unroll
            for (int k = 0; k < 4; k++) acc[i][j][k] = 0.f;

    int wm = wid * 32;
    #pragma unroll
    for (int sstep = 0; sstep < 4; sstep++) {
        uint32_t a[2][4], bg[4][4];
        #pragma unroll
        for (int mt = 0; mt < 2; mt++) {
            int row = wm + mt * 16 + (lane & 15);
            uint32_t col = (uint32_t)(sstep * 32 + (lane >> 4) * 16);
            LDSM_X4(a[mt], abase + row * 128 + (col ^ ((row & 7) * 16)));
        }
        #pragma unroll
        for (int nt2 = 0; nt2 < 4; nt2++) {
            int rw = nt2 * 16 + (lane & 7) + ((lane >> 4) & 1) * 8;
            uint32_t cl = (uint32_t)(sstep * 32 + ((lane >> 3) & 1) * 16);
            LDSM_X4(bg[nt2], bbase + rw * 128 + (cl ^ ((rw & 7) * 16)));
        }
        #pragma unroll
        for (int mt = 0; mt < 2; mt++)
            #pragma unroll
            for (int nt = 0; nt < 8; nt++)
                mma16816(acc[mt][nt], a[mt],
                         bg[nt >> 1][(nt & 1) * 2], bg[nt >> 1][(nt & 1) * 2 + 1]);
    }

    int g = lane >> 2, tq = (lane & 3) * 2;
    #pragma unroll
    for (int mt = 0; mt < 2; mt++) {
        int row = wm + mt * 16 + g;
        #pragma unroll
        for (int nt = 0; nt < 8; nt++) {
            int col = h * 64 + nt * 8 + tq;
            size_t o0 = ((size_t)b * N_ + n0 + row) * C_ + col;
            size_t o1 = ((size_t)b * N_ + n0 + row + 8) * C_ + col;
            *reinterpret_cast<__nv_bfloat162*>(&g_at[o0]) =
                __floats2bfloat162_rn(acc[mt][nt][0], acc[mt][nt][1]);
            *reinterpret_cast<__nv_bfloat162*>(&g_at[o1]) =
                __floats2bfloat162_rn(acc[mt][nt][2], acc[mt][nt][3]);
        }
    }
}

// ------------------------- launch ------------------------------------------
extern "C" void kernel_launch(void* const* d_in, const int* in_sizes, int n_in,
                              void* d_out, int out_size) {
    const float* x     = (const float*)d_in[0];
    const float* gn_w  = (const float*)d_in[1];
    const float* gn_b  = (const float*)d_in[2];
    const float* qkv_w = (const float*)d_in[3];
    const float* qkv_b = (const float*)d_in[4];
    const float* out_w = (const float*)d_in[5];
    const float* out_b = (const float*)d_in[6];
    float* y = (float*)d_out;

    cudaFuncSetAttribute(hmma_gemm_kernel, cudaFuncAttributeMaxDynamicSharedMemorySize,
                         GEMM_SMEM_BYTES);

    pre_kernel<<<1536, 256>>>(x, qkv_w, out_w);
    gn_apply_t_kernel<<<dim3(N_ / 64, C_ / 64, B_), 256>>>(x, gn_w, gn_b);
    hmma_gemm_kernel<<<dim3(N_ / 128, K3 / 128, B_), 128, GEMM_SMEM_BYTES>>>(
        qkv_b, nullptr, nullptr, K3, 0);
    context_hmma_kernel<<<1536, 128>>>();
    apply_ctx_fused_kernel<<<dim3(N_ / 128, NH_, B_), 128>>>();
    hmma_gemm_kernel<<<dim3(N_ / 128, C_ / 128, B_), 128, GEMM_SMEM_BYTES>>>(
        out_b, y, x, C_, 1);
}

// round 16
// speedup vs baseline: 1.2479x; 1.2479x over previous
#include <cuda_runtime.h>
#include <cuda_bf16.h>
#include <math.h>
#include <stdint.h>

#define B_   16
#define C_   256
#define N_   4096
#define NH_  4
#define HD_  64
#define G_   32
#define K3   768   // 3*C
#define NSPLIT 8

// ------------------------- scratch (device globals; no allocation) ---------
__device__ float g_mean[B_ * G_];
__device__ float g_rstd[B_ * G_];
__device__ __nv_bfloat16 g_ht[(size_t)B_ * N_ * C_];   // GN out, [b][n][c] bf16
__device__ __nv_bfloat16 g_at[(size_t)B_ * N_ * C_];   // attn out, [b][n][c] bf16
__device__ __nv_bfloat16 g_qkvh[(size_t)B_ * K3 * N_]; // qkv, [b][768][n] bf16
__device__ float2 g_qpart[B_ * C_ * 64];               // per-(row, chunk) partial {max, sumexp}
__device__ float2 g_qstat[B_ * C_];                    // per-(b,c) q row: {max, 1/sumexp}
__device__ float g_ctxp[(size_t)NSPLIT * B_ * NH_ * HD_ * HD_];
__device__ __nv_bfloat16 g_ctxT[B_ * NH_ * HD_ * HD_]; // reduced ctx^T, [b][h][e][d] bf16
__device__ __nv_bfloat16 g_wqkv[K3 * C_];
__device__ __nv_bfloat16 g_wout[C_ * C_];

// ------------------------- helpers -----------------------------------------
__device__ __forceinline__ uint32_t smem_u32(const void* p) {
    uint32_t a;
    asm("{ .reg .u64 t; cvta.to.shared.u64 t, %1; cvt.u32.u64 %0, t; }" : "=r"(a) : "l"(p));
    return a;
}

#define LDSM_X4(r, addr) \
    asm volatile("ldmatrix.sync.aligned.m8n8.x4.shared.b16 {%0,%1,%2,%3}, [%4];" \
        : "=r"((r)[0]), "=r"((r)[1]), "=r"((r)[2]), "=r"((r)[3]) : "r"(addr))

__device__ __forceinline__ void mma16816(float* c, const uint32_t* a,
                                         uint32_t b0, uint32_t b1) {
    asm volatile(
        "mma.sync.aligned.m16n8k16.row.col.f32.bf16.bf16.f32 "
        "{%0,%1,%2,%3}, {%4,%5,%6,%7}, {%8,%9}, {%0,%1,%2,%3};"
        : "+f"(c[0]), "+f"(c[1]), "+f"(c[2]), "+f"(c[3])
        : "r"(a[0]), "r"(a[1]), "r"(a[2]), "r"(a[3]), "r"(b0), "r"(b1));
}

__device__ __forceinline__ float warpReduceSum(float v) {
    #pragma unroll
    for (int o = 16; o > 0; o >>= 1) v += __shfl_xor_sync(0xffffffffu, v, o);
    return v;
}
__device__ __forceinline__ float warpReduceMax(float v) {
    #pragma unroll
    for (int o = 16; o > 0; o >>= 1) v = fmaxf(v, __shfl_xor_sync(0xffffffffu, v, o));
    return v;
}

// ------------------------- 1. merged: GroupNorm stats + weight convert -----
__global__ void pre_kernel(const float* __restrict__ x,
                           const float* __restrict__ qkv_w,
                           const float* __restrict__ out_w) {
    if (blockIdx.x >= 512) {
        int i = (blockIdx.x - 512) * 256 + threadIdx.x;
        if (i < K3 * C_) g_wqkv[i] = __float2bfloat16(qkv_w[i]);
        else             g_wout[i - K3 * C_] = __float2bfloat16(out_w[i - K3 * C_]);
        return;
    }
    int bg = blockIdx.x;
    const float4* p = reinterpret_cast<const float4*>(x) + (size_t)bg * 8192;
    float s = 0.f, ss = 0.f;
    for (int i = threadIdx.x; i < 8192; i += 256) {
        float4 v = p[i];
        s  += v.x + v.y + v.z + v.w;
        ss += v.x * v.x + v.y * v.y + v.z * v.z + v.w * v.w;
    }
    __shared__ float sm1[8], sm2[8];
    s  = warpReduceSum(s);
    ss = warpReduceSum(ss);
    int w = threadIdx.x >> 5, l = threadIdx.x & 31;
    if (l == 0) { sm1[w] = s; sm2[w] = ss; }
    __syncthreads();
    if (threadIdx.x == 0) {
        float S = 0.f, SS = 0.f;
        #pragma unroll
        for (int i = 0; i < 8; i++) { S += sm1[i]; SS += sm2[i]; }
        float m   = S * (1.f / 32768.f);
        float var = SS * (1.f / 32768.f) - m * m;
        g_mean[bg] = m;
        g_rstd[bg] = rsqrtf(var + 1e-5f);
    }
}

// ------------------------- 2. GroupNorm apply + transpose to bf16 ----------
__global__ void gn_apply_t_kernel(const float* __restrict__ x,
                                  const float* __restrict__ gw,
                                  const float* __restrict__ gb) {
    __shared__ float s[64][65];
    int b = blockIdx.z, c0 = blockIdx.y * 64, n0 = blockIdx.x * 64;
    int tid = threadIdx.x;
    #pragma unroll
    for (int i = 0; i < 4; i++) {
        int idx = i * 256 + tid;
        int c = idx >> 4, nq = idx & 15;
        int cc = c0 + c;
        int bg = b * G_ + (cc >> 3);
        float sc = gw[cc] * g_rstd[bg];
        float sh = gb[cc] - g_mean[bg] * sc;
        float4 v = *reinterpret_cast<const float4*>(&x[((size_t)b * C_ + cc) * N_ + n0 + nq * 4]);
        s[c][nq * 4 + 0] = v.x * sc + sh;
        s[c][nq * 4 + 1] = v.y * sc + sh;
        s[c][nq * 4 + 2] = v.z * sc + sh;
        s[c][nq * 4 + 3] = v.w * sc + sh;
    }
    __syncthreads();
    #pragma unroll
    for (int i = 0; i < 2; i++) {
        int idx = i * 256 + tid;
        int n = idx >> 3, cq = idx & 7;
        __nv_bfloat16 tmp[8];
        #pragma unroll
        for (int j = 0; j < 8; j++) tmp[j] = __float2bfloat16(s[cq * 8 + j][n]);
        *reinterpret_cast<uint4*>(&g_ht[((size_t)b * N_ + n0 + n) * C_ + c0 + cq * 8]) =
            *reinterpret_cast<uint4*>(tmp);
    }
}

// ------------------------- 3. HMMA bf16 GEMM + fused q-stat partials -------
#define GEMM_SMEM_BYTES 65536

__global__ __launch_bounds__(128) void hmma_gemm_kernel(
    const float* __restrict__ bias, float* __restrict__ Cout_ext,
    const float* __restrict__ Resid, int Mtotal, int which)
{
    extern __shared__ char smem[];
    const __nv_bfloat16* W    = which ? g_wout : g_wqkv;
    const __nv_bfloat16* Bact = which ? g_at   : g_ht;

    int b = blockIdx.z;
    int m0 = blockIdx.y * 128, n0 = blockIdx.x * 128;
    int tid = threadIdx.x, lane = tid & 31, wid = tid >> 5;
    int wm = (wid >> 1) * 64, wn = (wid & 1) * 64;

    const __nv_bfloat16* Asrc = W + (size_t)m0 * C_;
    const __nv_bfloat16* Bsrc = Bact + ((size_t)b * N_ + n0) * C_;
    uint32_t sbase = smem_u32(smem);

    auto issue = [&](int buf, int k0) {
        uint32_t abase = sbase + buf * 32768;
        uint32_t bbase = abase + 16384;
        #pragma unroll
        for (int i = 0; i < 8; i++) {
            int j = i * 128 + tid;
            int r = j >> 3, q = j & 7;
            uint32_t sw = (uint32_t)((q * 16) ^ ((r & 7) * 16));
            const void* sa = Asrc + (size_t)r * C_ + k0 + q * 8;
            const void* sb = Bsrc + (size_t)r * C_ + k0 + q * 8;
            asm volatile("cp.async.cg.shared.global [%0], [%1], 16;" :: "r"(abase + r * 128 + sw), "l"(sa));
            asm volatile("cp.async.cg.shared.global [%0], [%1], 16;" :: "r"(bbase + r * 128 + sw), "l"(sb));
        }
        asm volatile("cp.async.commit_group;" ::: "memory");
    };

    float acc[4][8][4];
    #pragma unroll
    for (int i = 0; i < 4; i++)
        #pragma unroll
        for (int j = 0; j < 8; j++)
            #pragma unroll
            for (int k = 0; k < 4; k++) acc[i][j][k] = 0.f;

    issue(0, 0);

    #pragma unroll
    for (int kt = 0; kt < 4; kt++) {
        if (kt < 3) {
            issue((kt + 1) & 1, (kt + 1) * 64);
            asm volatile("cp.async.wait_group 1;" ::: "memory");
        } else {
            asm volatile("cp.async.wait_group 0;" ::: "memory");
        }
        __syncthreads();
        uint32_t abase = sbase + (kt & 1) * 32768;
        uint32_t bbase = abase + 16384;
        #pragma unroll
        for (int s = 0; s < 4; s++) {
            uint32_t a[4][4], bg[4][4];
            #pragma unroll
            for (int mt = 0; mt < 4; mt++) {
                int row = wm + mt * 16 + (lane & 15);
                uint32_t col = (uint32_t)(s * 32 + (lane >> 4) * 16);
                LDSM_X4(a[mt], abase + row * 128 + (col ^ ((row & 7) * 16)));
            }
            #pragma unroll
            for (int nt2 = 0; nt2 < 4; nt2++) {
                int row = wn + nt2 * 16 + (lane & 7) + ((lane >> 4) & 1) * 8;
                uint32_t col = (uint32_t)(s * 32 + ((lane >> 3) & 1) * 16);
                LDSM_X4(bg[nt2], bbase + row * 128 + (col ^ ((row & 7) * 16)));
            }
            #pragma unroll
            for (int mt = 0; mt < 4; mt++)
                #pragma unroll
                for (int nt = 0; nt < 8; nt++)
                    mma16816(acc[mt][nt], a[mt],
                             bg[nt >> 1][(nt & 1) * 2], bg[nt >> 1][(nt & 1) * 2 + 1]);
        }
        __syncthreads();
    }

    size_t cb = (size_t)b * Mtotal * N_;
    int g = lane >> 2, tq = (lane & 3) * 2;
    #pragma unroll
    for (int mt = 0; mt < 4; mt++) {
        int rbase = m0 + wm + mt * 16 + g;
        float bv0 = bias[rbase], bv1 = bias[rbase + 8];
        #pragma unroll
        for (int nt = 0; nt < 8; nt++) {
            int cl = n0 + wn + nt * 8 + tq;
            size_t o0 = cb + (size_t)rbase * N_ + cl;
            size_t o1 = o0 + (size_t)8 * N_;
            if (which == 0) {
                *reinterpret_cast<__nv_bfloat162*>(&g_qkvh[o0]) =
                    __floats2bfloat162_rn(acc[mt][nt][0] + bv0, acc[mt][nt][1] + bv0);
                *reinterpret_cast<__nv_bfloat162*>(&g_qkvh[o1]) =
                    __floats2bfloat162_rn(acc[mt][nt][2] + bv1, acc[mt][nt][3] + bv1);
            } else {
                float2 r0 = *reinterpret_cast<const float2*>(&Resid[o0]);
                float2 r1 = *reinterpret_cast<const float2*>(&Resid[o1]);
                float2 v0 = make_float2(acc[mt][nt][0] + bv0 + r0.x, acc[mt][nt][1] + bv0 + r0.y);
                float2 v1 = make_float2(acc[mt][nt][2] + bv1 + r1.x, acc[mt][nt][3] + bv1 + r1.y);
                *reinterpret_cast<float2*>(&Cout_ext[o0]) = v0;
                *reinterpret_cast<float2*>(&Cout_ext[o1]) = v1;
            }
        }
        // fused partial q-softmax stats for q rows (m < 256)
        if (which == 0 && m0 < 256) {
            float m0f = -1e30f, m1f = -1e30f;
            #pragma unroll
            for (int nt = 0; nt < 8; nt++) {
                m0f = fmaxf(m0f, fmaxf(acc[mt][nt][0], acc[mt][nt][1]));
                m1f = fmaxf(m1f, fmaxf(acc[mt][nt][2], acc[mt][nt][3]));
            }
            m0f += bv0; m1f += bv1;
            float s0 = 0.f, s1 = 0.f;
            #pragma unroll
            for (int nt = 0; nt < 8; nt++) {
                s0 += __expf(acc[mt][nt][0] + bv0 - m0f) + __expf(acc[mt][nt][1] + bv0 - m0f);
                s1 += __expf(acc[mt][nt][2] + bv1 - m1f) + __expf(acc[mt][nt][3] + bv1 - m1f);
            }
            #pragma unroll
            for (int off = 1; off < 4; off <<= 1) {
                float mo0 = __shfl_xor_sync(0xffffffffu, m0f, off);
                float so0 = __shfl_xor_sync(0xffffffffu, s0, off);
                float nm0 = fmaxf(m0f, mo0);
                s0 = s0 * __expf(m0f - nm0) + so0 * __expf(mo0 - nm0);
                m0f = nm0;
                float mo1 = __shfl_xor_sync(0xffffffffu, m1f, off);
                float so1 = __shfl_xor_sync(0xffffffffu, s1, off);
                float nm1 = fmaxf(m1f, mo1);
                s1 = s1 * __expf(m1f - nm1) + so1 * __expf(mo1 - nm1);
                m1f = nm1;
            }
            if ((lane & 3) == 0) {
                int chunk = (n0 >> 7) * 2 + (wn >> 6);
                g_qpart[(b * 256 + rbase) * 64 + chunk]     = make_float2(m0f, s0);
                g_qpart[(b * 256 + rbase + 8) * 64 + chunk] = make_float2(m1f, s1);
            }
        }
    }
}

// ------------------------- 4. context = softmax_d(K) @ V^T (HMMA, fused) ---
__global__ __launch_bounds__(128) void context_hmma_kernel() {
    __shared__ char smem[32768];
    int ns = blockIdx.x, h = blockIdx.y, b = blockIdx.z;
    const __nv_bfloat16* Kp = g_qkvh + ((size_t)b * K3 + 256 + h * 64) * N_;
    const __nv_bfloat16* Vp = g_qkvh + ((size_t)b * K3 + 512 + h * 64) * N_;
    int tid = threadIdx.x, lane = tid & 31, wid = tid >> 5;
    uint32_t sbase = smem_u32(smem);
    int n0 = ns * (N_ / NSPLIT);

    auto issue = [&](int buf, int k0) {
        uint32_t kb = sbase + buf * 16384;
        uint32_t vb = kb + 8192;
        #pragma unroll
        for (int i = 0; i < 4; i++) {
            int j = i * 128 + tid;
            int r = j >> 3, q = j & 7;
            uint32_t sw = (uint32_t)((q * 16) ^ ((r & 7) * 16));
            const void* sk = Kp + (size_t)r * N_ + k0 + q * 8;
            const void* sv = Vp + (size_t)r * N_ + k0 + q * 8;
            asm volatile("cp.async.cg.shared.global [%0], [%1], 16;" :: "r"(kb + r * 128 + sw), "l"(sk));
            asm volatile("cp.async.cg.shared.global [%0], [%1], 16;" :: "r"(vb + r * 128 + sw), "l"(sv));
        }
        asm volatile("cp.async.commit_group;" ::: "memory");
    };

    auto ktile_softmax = [&](uint32_t kb) {
        int colq = tid >> 1, half = tid & 1;
        __nv_bfloat16* ks = reinterpret_cast<__nv_bfloat16*>(smem) + (kb - sbase) / 2;
        float v[32];
        float mx = -1e30f;
        #pragma unroll
        for (int j = 0; j < 32; j++) {
            int d = half * 32 + j;
            uint32_t off = (uint32_t)(d * 128 + ((colq * 2) ^ ((d & 7) * 16)));
            v[j] = __bfloat162float(ks[off / 2]);
            mx = fmaxf(mx, v[j]);
        }
        mx = fmaxf(mx, __shfl_xor_sync(0xffffffffu, mx, 1));
        float s = 0.f;
        #pragma unroll
        for (int j = 0; j < 32; j++) { v[j] = __expf(v[j] - mx); s += v[j]; }
        s += __shfl_xor_sync(0xffffffffu, s, 1);
        float inv = 1.f / s;
        #pragma unroll
        for (int j = 0; j < 32; j++) {
            int d = half * 32 + j;
            uint32_t off = (uint32_t)(d * 128 + ((colq * 2) ^ ((d & 7) * 16)));
            ks[off / 2] = __float2bfloat16(v[j] * inv);
        }
    };

    float acc[8][4];
    #pragma unroll
    for (int i = 0; i < 8; i++)
        #pragma unroll
        for (int j = 0; j < 4; j++) acc[i][j] = 0.f;

    issue(0, n0);
    #pragma unroll
    for (int kt = 0; kt < 8; kt++) {
        if (kt < 7) {
            issue((kt + 1) & 1, n0 + (kt + 1) * 64);
            asm volatile("cp.async.wait_group 1;" ::: "memory");
        } else {
            asm volatile("cp.async.wait_group 0;" ::: "memory");
        }
        __syncthreads();
        uint32_t kb = sbase + (kt & 1) * 16384;
        uint32_t vb = kb + 8192;
        ktile_softmax(kb);
        __syncthreads();
        #pragma unroll
        for (int s = 0; s < 4; s++) {
            uint32_t a[4], bg[4][4];
            int row = wid * 16 + (lane & 15);
            uint32_t col = (uint32_t)(s * 32 + (lane >> 4) * 16);
            LDSM_X4(a, kb + row * 128 + (col ^ ((row & 7) * 16)));
            #pragma unroll
            for (int nt2 = 0; nt2 < 4; nt2++) {
                int rw = nt2 * 16 + (lane & 7) + ((lane >> 4) & 1) * 8;
                uint32_t cl = (uint32_t)(s * 32 + ((lane >> 3) & 1) * 16);
                LDSM_X4(bg[nt2], vb + rw * 128 + (cl ^ ((rw & 7) * 16)));
            }
            #pragma unroll
            for (int nt = 0; nt < 8; nt++)
                mma16816(acc[nt], a, bg[nt >> 1][(nt & 1) * 2], bg[nt >> 1][(nt & 1) * 2 + 1]);
        }
        __syncthreads();
    }
    float* cp = g_ctxp + (((size_t)ns * B_ + b) * NH_ + h) * (HD_ * HD_);
    int g = lane >> 2, tq = (lane & 3) * 2;
    int row = wid * 16 + g;
    #pragma unroll
    for (int nt = 0; nt < 8; nt++) {
        int col = nt * 8 + tq;
        cp[row * 64 + col]           = acc[nt][0];
        cp[row * 64 + col + 1]       = acc[nt][1];
        cp[(row + 8) * 64 + col]     = acc[nt][2];
        cp[(row + 8) * 64 + col + 1] = acc[nt][3];
    }
}

// ------------------------- 5. merged skinny: qstat2 + ctx_reduce -----------
// blocks [0,512): qstat2 (8 rows/block via 8 warps)... wait 512*8=4096 rows OK
// blocks [512,576): ctx_reduce for bh = bid-512
__global__ __launch_bounds__(256) void tail_reduce_kernel() {
    int bid = blockIdx.x;
    int tid = threadIdx.x, wid = tid >> 5, lane = tid & 31;
    if (bid < 512) {
        int row = bid * 8 + wid;          // 4096 rows
        float2 a = g_qpart[row * 64 + lane];
        float2 c = g_qpart[row * 64 + 32 + lane];
        float m = fmaxf(a.x, c.x);
        float s = a.y * __expf(a.x - m) + c.y * __expf(c.x - m);
        #pragma unroll
        for (int off = 16; off > 0; off >>= 1) {
            float mo = __shfl_xor_sync(0xffffffffu, m, off);
            float so = __shfl_xor_sync(0xffffffffu, s, off);
            float nm = fmaxf(m, mo);
            s = s * __expf(m - nm) + so * __expf(mo - nm);
            m = nm;
        }
        if (lane == 0) g_qstat[row] = make_float2(m, 1.f / s);
        return;
    }
    int bh = bid - 512;
    int base = bh * (HD_ * HD_);
    for (int i = tid; i < HD_ * HD_; i += 256) {
        int e = i >> 6, d = i & 63;
        float s = 0.f;
        #pragma unroll
        for (int sp = 0; sp < NSPLIT; sp++)
            s += g_ctxp[(size_t)sp * B_ * NH_ * HD_ * HD_ + base + d * 64 + e];
        g_ctxT[base + i] = __float2bfloat16(s);   // [e][d]
    }
}

// ------------------------- 6. fused softmax(q)+transpose + ctx GEMM --------
__global__ __launch_bounds__(128) void apply_ctx_fused_kernel() {
    __shared__ float s[64][65];
    __shared__ float2 st[64];
    __shared__ char asmem[16384];
    __shared__ char bsmem[8192];
    int b = blockIdx.z, h = blockIdx.y, n0 = blockIdx.x * 128;
    int tid = threadIdx.x, lane = tid & 31, wid = tid >> 5;
    uint32_t abase = smem_u32(asmem), bbase = smem_u32(bsmem);

    const __nv_bfloat16* Qp = g_qkvh + ((size_t)b * K3 + h * 64) * N_;
    const __nv_bfloat16* Bp = g_ctxT + (b * NH_ + h) * (HD_ * HD_);

    #pragma unroll
    for (int i = 0; i < 4; i++) {
        int j = i * 128 + tid;
        int r = j >> 3, q = j & 7;
        uint32_t sw = (uint32_t)((q * 16) ^ ((r & 7) * 16));
        const void* sb = Bp + (size_t)r * HD_ + q * 8;
        asm volatile("cp.async.cg.shared.global [%0], [%1], 16;" :: "r"(bbase + r * 128 + sw), "l"(sb));
    }
    asm volatile("cp.async.commit_group;" ::: "memory");

    if (tid < 64) st[tid] = g_qstat[b * 256 + h * 64 + tid];

    #pragma unroll
    for (int half = 0; half < 2; half++) {
        int nh = n0 + half * 64;
        __syncthreads();
        #pragma unroll
        for (int i = 0; i < 4; i++) {
            int j = i * 128 + tid;
            int r = j >> 3, q8 = j & 7;
            uint4 u = *reinterpret_cast<const uint4*>(&Qp[(size_t)r * N_ + nh + q8 * 8]);
            const __nv_bfloat162* hh = reinterpret_cast<const __nv_bfloat162*>(&u);
            float2 ms = st[r];
            #pragma unroll
            for (int k = 0; k < 4; k++) {
                float2 f = __bfloat1622float2(hh[k]);
                s[r][q8 * 8 + 2 * k]     = __expf(f.x - ms.x) * ms.y;
                s[r][q8 * 8 + 2 * k + 1] = __expf(f.y - ms.x) * ms.y;
            }
        }
        __syncthreads();
        #pragma unroll
        for (int i = 0; i < 4; i++) {
            int j = i * 128 + tid;
            int n = j >> 3, cq = j & 7;
            __nv_bfloat16 tmp[8];
            #pragma unroll
            for (int k = 0; k < 8; k++) tmp[k] = __float2bfloat16(s[cq * 8 + k][n]);
            int row = half * 64 + n;
            uint32_t sw = (uint32_t)((cq * 16) ^ ((row & 7) * 16));
            *reinterpret_cast<uint4*>(asmem + row * 128 + sw) = *reinterpret_cast<uint4*>(tmp);
        }
    }
    asm volatile("cp.async.wait_group 0;" ::: "memory");
    __syncthreads();

    float acc[2][8][4];
    #pragma unroll
    for (int i = 0; i < 2; i++)
        #pragma unroll
        for (int j = 0; j < 8; j++)
            #pragma unroll
            for (int k = 0; k < 4; k++) acc[i][j][k] = 0.f;

    int wm = wid * 32;
    #pragma unroll
    for (int sstep = 0; sstep < 4; sstep++) {
        uint32_t a[2][4], bg[4][4];
        #pragma unroll
        for (int mt = 0; mt < 2; mt++) {
            int row = wm + mt * 16 + (lane & 15);
            uint32_t col = (uint32_t)(sstep * 32 + (lane >> 4) * 16);
            LDSM_X4(a[mt], abase + row * 128 + (col ^ ((row & 7) * 16)));
        }
        #pragma unroll
        for (int nt2 = 0; nt2 < 4; nt2++) {
            int rw = nt2 * 16 + (lane & 7) + ((lane >> 4) & 1) * 8;
            uint32_t cl = (uint32_t)(sstep * 32 + ((lane >> 3) & 1) * 16);
            LDSM_X4(bg[nt2], bbase + rw * 128 + (cl ^ ((rw & 7) * 16)));
        }
        #pragma unroll
        for (int mt = 0; mt < 2; mt++)
            #pragma unroll
            for (int nt = 0; nt < 8; nt++)
                mma16816(acc[mt][nt], a[mt],
                         bg[nt >> 1][(nt & 1) * 2], bg[nt >> 1][(nt & 1) * 2 + 1]);
    }

    int g = lane >> 2, tq = (lane & 3) * 2;
    #pragma unroll
    for (int mt = 0; mt < 2; mt++) {
        int row = wm + mt * 16 + g;
        #pragma unroll
        for (int nt = 0; nt < 8; nt++) {
            int col = h * 64 + nt * 8 + tq;
            size_t o0 = ((size_t)b * N_ + n0 + row) * C_ + col;
            size_t o1 = ((size_t)b * N_ + n0 + row + 8) * C_ + col;
            *reinterpret_cast<__nv_bfloat162*>(&g_at[o0]) =
                __floats2bfloat162_rn(acc[mt][nt][0], acc[mt][nt][1]);
            *reinterpret_cast<__nv_bfloat162*>(&g_at[o1]) =
                __floats2bfloat162_rn(acc[mt][nt][2], acc[mt][nt][3]);
        }
    }
}

// ------------------------- launch ------------------------------------------
extern "C" void kernel_launch(void* const* d_in, const int* in_sizes, int n_in,
                              void* d_out, int out_size) {
    const float* x     = (const float*)d_in[0];
    const float* gn_w  = (const float*)d_in[1];
    const float* gn_b  = (const float*)d_in[2];
    const float* qkv_w = (const float*)d_in[3];
    const float* qkv_b = (const float*)d_in[4];
    const float* out_w = (const float*)d_in[5];
    const float* out_b = (const float*)d_in[6];
    float* y = (float*)d_out;

    cudaFuncSetAttribute(hmma_gemm_kernel, cudaFuncAttributeMaxDynamicSharedMemorySize,
                         GEMM_SMEM_BYTES);

    pre_kernel<<<1536, 256>>>(x, qkv_w, out_w);
    gn_apply_t_kernel<<<dim3(N_ / 64, C_ / 64, B_), 256>>>(x, gn_w, gn_b);
    hmma_gemm_kernel<<<dim3(N_ / 128, K3 / 128, B_), 128, GEMM_SMEM_BYTES>>>(
        qkv_b, nullptr, nullptr, K3, 0);
    context_hmma_kernel<<<dim3(NSPLIT, NH_, B_), 128>>>();
    tail_reduce_kernel<<<576, 256>>>();
    apply_ctx_fused_kernel<<<dim3(N_ / 128, NH_, B_), 128>>>();
    hmma_gemm_kernel<<<dim3(N_ / 128, C_ / 128, B_), 128, GEMM_SMEM_BYTES>>>(
        out_b, y, x, C_, 1);
}